// round 3
// baseline (speedup 1.0000x reference)
#include <cuda_runtime.h>
#include <math.h>

#define NBATCH 64
#define NT     512
#define NROWS  (NBATCH * NT)

// ---------------- device scratch (no allocations allowed) ----------------
__device__ float g_pre1[NROWS * 1024];
__device__ float g_pre2[NROWS * 512];
__device__ float g_v1all[NROWS * 1024];
__device__ float g_memall[NROWS * 256];
__device__ float g_v1T[1024 * 64];          // [h][b]
__device__ float g_memT[2][256 * 64];       // [m][b] double-buffered
__device__ float g_Apart[8 * 1024 * 64];    // [mc][h][b]
__device__ float g_Bpart[24 * 128 * 64];    // [kc][o][b]
__device__ float g_bias1[1024];
__device__ float g_bias2[512];
__device__ unsigned g_barCnt;

// ---------------- prep: fused biases, initial memory transpose ----------------
__global__ void prep_kernel(const float* __restrict__ b01, const float* __restrict__ bm1,
                            const float* __restrict__ b02, const float* __restrict__ b12,
                            const float* __restrict__ bm2, const float* __restrict__ memory) {
    int i = blockIdx.x * blockDim.x + threadIdx.x;
    int n = gridDim.x * blockDim.x;
    if (i == 0) g_barCnt = 0u;
    for (int j = i; j < 1024; j += n) g_bias1[j] = b01[j] + bm1[j];
    for (int j = i; j < 512; j += n) g_bias2[j] = b02[j] + b12[j] + bm2[j];
    for (int j = i; j < 256 * 64; j += n) {
        int m = j >> 6, b = j & 63;
        g_memT[0][j] = memory[b * 256 + m];
    }
}

// ---------------- fp32 GEMM helper: acc += A[64xK] * B[64xK]^T tile ----------------
// A row-major [M x K] (lda=K), Bm row-major [N x K] (ldb=K). 256 threads, 4x4 micro.
__device__ __forceinline__ void gemm_acc(const float* __restrict__ A, int lda,
                                         const float* __restrict__ Bm, int ldb, int K,
                                         int m0, int n0, float acc[4][4]) {
    __shared__ float As[16][68];
    __shared__ float Bs[16][68];
    int tid = threadIdx.x;
    int lrow = tid >> 2, kq = (tid & 3) * 4;
    int ty = tid >> 4, tx = tid & 15;
    for (int kt = 0; kt < K; kt += 16) {
        float4 a4 = *(const float4*)&A[(m0 + lrow) * lda + kt + kq];
        float4 b4 = *(const float4*)&Bm[(n0 + lrow) * ldb + kt + kq];
        __syncthreads();
        As[kq + 0][lrow] = a4.x; As[kq + 1][lrow] = a4.y;
        As[kq + 2][lrow] = a4.z; As[kq + 3][lrow] = a4.w;
        Bs[kq + 0][lrow] = b4.x; Bs[kq + 1][lrow] = b4.y;
        Bs[kq + 2][lrow] = b4.z; Bs[kq + 3][lrow] = b4.w;
        __syncthreads();
#pragma unroll
        for (int k = 0; k < 16; k++) {
            float4 av = *(float4*)&As[k][ty * 4];
            float4 bv = *(float4*)&Bs[k][tx * 4];
            acc[0][0] += av.x * bv.x; acc[0][1] += av.x * bv.y;
            acc[0][2] += av.x * bv.z; acc[0][3] += av.x * bv.w;
            acc[1][0] += av.y * bv.x; acc[1][1] += av.y * bv.y;
            acc[1][2] += av.y * bv.z; acc[1][3] += av.y * bv.w;
            acc[2][0] += av.z * bv.x; acc[2][1] += av.z * bv.y;
            acc[2][2] += av.z * bv.z; acc[2][3] += av.z * bv.w;
            acc[3][0] += av.w * bv.x; acc[3][1] += av.w * bv.y;
            acc[3][2] += av.w * bv.z; acc[3][3] += av.w * bv.w;
        }
    }
}

__global__ void __launch_bounds__(256) pre_kernel(const float* __restrict__ A,
                                                  const float* __restrict__ W, int N, int K,
                                                  const float* __restrict__ bias,
                                                  float* __restrict__ C) {
    int m0 = blockIdx.x * 64, n0 = blockIdx.y * 64;
    int ty = threadIdx.x >> 4, tx = threadIdx.x & 15;
    float acc[4][4] = {};
    gemm_acc(A, K, W, K, K, m0, n0, acc);
    float4 bb = *(const float4*)&bias[n0 + tx * 4];
#pragma unroll
    for (int i = 0; i < 4; i++) {
        int row = m0 + ty * 4 + i;
        float4 o4 = make_float4(acc[i][0] + bb.x, acc[i][1] + bb.y,
                                acc[i][2] + bb.z, acc[i][3] + bb.w);
        *(float4*)&C[row * N + n0 + tx * 4] = o4;
    }
}

// tail: out[:, :, 128:512] = pre2 + v1all @ W12[128:]^T + memall @ Wm2[128:]^T
__global__ void __launch_bounds__(256) tail_kernel(const float* __restrict__ W12,
                                                   const float* __restrict__ Wm2,
                                                   float* __restrict__ out) {
    int m0 = blockIdx.x * 64, n0 = blockIdx.y * 64;
    int ty = threadIdx.x >> 4, tx = threadIdx.x & 15;
    float acc[4][4] = {};
    gemm_acc(g_v1all, 1024, W12 + 128 * 1024, 1024, 1024, m0, n0, acc);
    gemm_acc(g_memall, 256, Wm2 + 128 * 256, 256, 256, m0, n0, acc);
#pragma unroll
    for (int i = 0; i < 4; i++) {
        int row = m0 + ty * 4 + i;
        float4 p4 = *(const float4*)&g_pre2[row * 512 + 128 + n0 + tx * 4];
        float4 o4 = make_float4(acc[i][0] + p4.x, acc[i][1] + p4.y,
                                acc[i][2] + p4.z, acc[i][3] + p4.w);
        *(float4*)&out[row * 512 + 128 + n0 + tx * 4] = o4;
    }
}

// ---------------- persistent recurrent loop ----------------
__device__ __forceinline__ void gbar(unsigned target) {
    __syncthreads();
    if (threadIdx.x == 0) {
        __threadfence();
        atomicAdd(&g_barCnt, 1u);
        while (*(volatile unsigned*)&g_barCnt < target) { }
    }
    __syncthreads();
}

__global__ void __launch_bounds__(256, 1) loop_kernel(const float* __restrict__ Wm1,
                                                      const float* __restrict__ W12,
                                                      const float* __restrict__ Wm2,
                                                      float* __restrict__ out) {
    __shared__ float sIn[64 * 64];    // A: mem slice 32x64 | B: v1 slice 64x64
    __shared__ float sWA[32 * 64];    // Wm1 slice [m][h]
    __shared__ float sWB[64 * 16];    // W12 slice [k][o]
    __shared__ float sWC[32 * 8];     // Wm2 head slice [m][o]

    const int tid = threadIdx.x, blk = blockIdx.x;
    const int ht = blk >> 3, mcc = blk & 7;   // phase A: 16 h-tiles x 8 m-chunks
    const int otile = blk >> 4, kc = blk & 15; // phase B: 8 o-tiles x 16 k-chunks
    const int hy = tid >> 4, bx = tid & 15;   // 16x16 grid (phase A)
    const int oy = tid >> 5, b2 = tid & 31;   // 8x32 grid (phase B)

    // one-time weight staging (persists across all 512 steps)
    for (int i = tid; i < 32 * 64; i += 256) {
        int m = i >> 6, h = i & 63;
        sWA[i] = Wm1[(ht * 64 + h) * 256 + mcc * 32 + m];
    }
    for (int i = tid; i < 64 * 16; i += 256) {
        int k = i >> 4, o = i & 15;
        sWB[i] = W12[(otile * 16 + o) * 1024 + kc * 64 + k];
    }
    for (int i = tid; i < 32 * 8; i += 256) {
        int m = i >> 3, o = i & 7;
        sWC[i] = Wm2[(ht * 8 + o) * 256 + mcc * 32 + m];
    }
    __syncthreads();

    unsigned tgt = 128;
    for (int t = 0; t < NT; t++) {
        const int par = t & 1, nxt = par ^ 1;
        // ===== Phase A: stage mem slice, log memall, v1 partials + v2head-mem partials
        for (int i = tid; i < 512; i += 256) {
            int m = i >> 4, b4 = (i & 15) * 4;
            *(float4*)&sIn[m * 64 + b4] = __ldcg((const float4*)&g_memT[par][(mcc * 32 + m) * 64 + b4]);
        }
        __syncthreads();
        if (ht == 0) {
            for (int i = tid; i < 2048; i += 256) {
                int b = i >> 5, m = i & 31;
                __stcg(&g_memall[(b * NT + t) * 256 + mcc * 32 + m], sIn[m * 64 + b]);
            }
        }
        {
            float acc[4][4] = {};
#pragma unroll 8
            for (int m = 0; m < 32; m++) {
                float4 w = *(float4*)&sWA[m * 64 + hy * 4];
                float4 x = *(float4*)&sIn[m * 64 + bx * 4];
                acc[0][0] += w.x * x.x; acc[0][1] += w.x * x.y; acc[0][2] += w.x * x.z; acc[0][3] += w.x * x.w;
                acc[1][0] += w.y * x.x; acc[1][1] += w.y * x.y; acc[1][2] += w.y * x.z; acc[1][3] += w.y * x.w;
                acc[2][0] += w.z * x.x; acc[2][1] += w.z * x.y; acc[2][2] += w.z * x.z; acc[2][3] += w.z * x.w;
                acc[3][0] += w.w * x.x; acc[3][1] += w.w * x.y; acc[3][2] += w.w * x.z; acc[3][3] += w.w * x.w;
            }
#pragma unroll
            for (int i = 0; i < 4; i++)
                __stcg((float4*)&g_Apart[(mcc * 1024 + ht * 64 + hy * 4 + i) * 64 + bx * 4],
                       make_float4(acc[i][0], acc[i][1], acc[i][2], acc[i][3]));
        }
        {   // v2head mem contribution: o in [ht*8, ht*8+8), this mcc chunk
            int b = tid & 63, og = (tid >> 6) * 2;
            float a0 = 0.f, a1 = 0.f;
#pragma unroll 8
            for (int m = 0; m < 32; m++) {
                float x = sIn[m * 64 + b];
                a0 += sWC[m * 8 + og] * x;
                a1 += sWC[m * 8 + og + 1] * x;
            }
            __stcg(&g_Bpart[((16 + mcc) * 128 + ht * 8 + og) * 64 + b], a0);
            __stcg(&g_Bpart[((16 + mcc) * 128 + ht * 8 + og + 1) * 64 + b], a1);
        }
        gbar(tgt); tgt += 128;
        // ===== R1: reduce v1 partials + pre1, activations, write v1T/v1all/mem head
        {
            int b = tid >> 2, h0 = blk * 8 + (tid & 3) * 2;
            int row = b * NT + t;
            float2 p = __ldcg((const float2*)&g_pre1[row * 1024 + h0]);
            float s0 = p.x, s1 = p.y;
#pragma unroll
            for (int mc = 0; mc < 8; mc++) {
                s0 += __ldcg(&g_Apart[(mc * 1024 + h0) * 64 + b]);
                s1 += __ldcg(&g_Apart[(mc * 1024 + h0 + 1) * 64 + b]);
            }
            if (h0 < 512) { s0 = tanhf(s0); s1 = tanhf(s1); }
            else { s0 = fmaxf(s0, 0.f); s1 = fmaxf(s1, 0.f); }
            __stcg(&g_v1T[h0 * 64 + b], s0);
            __stcg(&g_v1T[(h0 + 1) * 64 + b], s1);
            __stcg((float2*)&g_v1all[row * 1024 + h0], make_float2(s0, s1));
            if (h0 < 128) {
                __stcg(&g_memT[nxt][h0 * 64 + b], s0);
                __stcg(&g_memT[nxt][(h0 + 1) * 64 + b], s1);
            }
        }
        gbar(tgt); tgt += 128;
        // ===== Phase B: v1 -> v2head partials (o-tile 16, k-chunk 64)
        for (int i = tid; i < 1024; i += 256) {
            int k = i >> 4, b4 = (i & 15) * 4;
            *(float4*)&sIn[k * 64 + b4] = __ldcg((const float4*)&g_v1T[(kc * 64 + k) * 64 + b4]);
        }
        __syncthreads();
        {
            float a00 = 0.f, a01 = 0.f, a10 = 0.f, a11 = 0.f;
#pragma unroll 8
            for (int k = 0; k < 64; k++) {
                float2 w = *(float2*)&sWB[k * 16 + oy * 2];
                float2 x = *(float2*)&sIn[k * 64 + b2 * 2];
                a00 += w.x * x.x; a01 += w.x * x.y;
                a10 += w.y * x.x; a11 += w.y * x.y;
            }
            int ob = (kc * 128 + otile * 16 + oy * 2) * 64 + b2 * 2;
            __stcg(&g_Bpart[ob], a00);       __stcg(&g_Bpart[ob + 1], a01);
            __stcg(&g_Bpart[ob + 64], a10);  __stcg(&g_Bpart[ob + 65], a11);
        }
        gbar(tgt); tgt += 128;
        // ===== R2: reduce 24 partials + pre2, sigmoid, write out head + mem tail
        if (tid < 64) {
            int o = blk, b = tid;
            int row = b * NT + t;
            float s = __ldcg(&g_pre2[row * 512 + o]);
#pragma unroll
            for (int p = 0; p < 24; p++) s += __ldcg(&g_Bpart[(p * 128 + o) * 64 + b]);
            s = 1.f / (1.f + expf(-s));
            __stcg(&out[row * 512 + o], s);
            __stcg(&g_memT[nxt][(128 + o) * 64 + b], s);
        }
        gbar(tgt); tgt += 128;
    }
}

// ---------------- launch ----------------
extern "C" void kernel_launch(void* const* d_in, const int* in_sizes, int n_in,
                              void* d_out, int out_size) {
    const float* X   = (const float*)d_in[0];
    const float* mem = (const float*)d_in[1];
    const float* W01 = (const float*)d_in[2];
    const float* b01 = (const float*)d_in[3];
    const float* W02 = (const float*)d_in[4];
    const float* b02 = (const float*)d_in[5];
    const float* W12 = (const float*)d_in[6];
    const float* b12 = (const float*)d_in[7];
    const float* Wm1 = (const float*)d_in[8];
    const float* bm1 = (const float*)d_in[9];
    const float* Wm2 = (const float*)d_in[10];
    const float* bm2 = (const float*)d_in[11];
    float* out = (float*)d_out;

    float *pre1, *pre2, *b1, *b2;
    cudaGetSymbolAddress((void**)&pre1, g_pre1);
    cudaGetSymbolAddress((void**)&pre2, g_pre2);
    cudaGetSymbolAddress((void**)&b1, g_bias1);
    cudaGetSymbolAddress((void**)&b2, g_bias2);

    prep_kernel<<<32, 256>>>(b01, bm1, b02, b12, bm2, mem);
    pre_kernel<<<dim3(NROWS / 64, 16), 256>>>(X, W01, 1024, 512, b1, pre1);
    pre_kernel<<<dim3(NROWS / 64, 8), 256>>>(X, W02, 512, 512, b2, pre2);
    loop_kernel<<<128, 256>>>(Wm1, W12, Wm2, out);
    tail_kernel<<<dim3(NROWS / 64, 6), 256>>>(W12, Wm2, out);
}

// round 6
// speedup vs baseline: 1.1215x; 1.1215x over previous
#include <cuda_runtime.h>
#include <cuda_bf16.h>
#include <cstdint>
#include <math.h>

#define NBATCH 64
#define NT     512
#define NROWS  (NBATCH * NT)

// ---------------- device scratch ----------------
__device__ float g_pre1[NROWS * 1024];
__device__ float g_pre2[NROWS * 512];
__device__ float g_v1all[NROWS * 1024];
__device__ float g_memall[NROWS * 256];
__device__ float g_v1T[1024 * 64];
__device__ float g_memT[2][256 * 64];
__device__ float g_Apart[8 * 1024 * 64];
__device__ float g_Bpart[24 * 128 * 64];
__device__ float g_bias1[1024];
__device__ float g_bias2[512];
__device__ unsigned g_barCnt;
// bf16 split operands (K-concat trick)
__device__ __nv_bfloat16 g_X3[NROWS * 1536];       // [Ah|Ah|Al]
__device__ __nv_bfloat16 g_W013[1024 * 1536];      // [Wh|Wl|Wh]
__device__ __nv_bfloat16 g_W023[512 * 1536];
__device__ __nv_bfloat16 g_Wt3[384 * 3840];
__device__ __nv_bfloat16 g_At3[NROWS * 3840];

// ---------------- prep ----------------
__global__ void prep_kernel(const float* __restrict__ b01, const float* __restrict__ bm1,
                            const float* __restrict__ b02, const float* __restrict__ b12,
                            const float* __restrict__ bm2, const float* __restrict__ memory) {
    int i = blockIdx.x * blockDim.x + threadIdx.x;
    int n = gridDim.x * blockDim.x;
    if (i == 0) g_barCnt = 0u;
    for (int j = i; j < 1024; j += n) g_bias1[j] = b01[j] + bm1[j];
    for (int j = i; j < 512; j += n) g_bias2[j] = b02[j] + b12[j] + bm2[j];
    for (int j = i; j < 256 * 64; j += n) {
        int m = j >> 6, b = j & 63;
        g_memT[0][j] = memory[b * 256 + m];
    }
}

// split fp32 -> bf16 hi/lo, K-concat. aMode: [h|h|l]  else (W): [h|l|h]
__global__ void split3_kernel(const float* __restrict__ src, __nv_bfloat16* __restrict__ dst,
                              int K, int total, int aMode) {
    for (int i = blockIdx.x * blockDim.x + threadIdx.x; i < total; i += gridDim.x * blockDim.x) {
        int r = i / K, k = i % K;
        float x = src[i];
        __nv_bfloat16 h = __float2bfloat16(x);
        __nv_bfloat16 l = __float2bfloat16(x - __bfloat162float(h));
        __nv_bfloat16* d = dst + (size_t)r * 3 * K + k;
        d[0] = h;
        d[K] = aMode ? h : l;
        d[2 * K] = aMode ? l : h;
    }
}

// tail W: rows o=0..383 map to W12[o+128], Wm2[o+128]; layout [Wh|Wl|Wh] over K=1280
__global__ void splitWtail_kernel(const float* __restrict__ W12, const float* __restrict__ Wm2) {
    for (int i = blockIdx.x * blockDim.x + threadIdx.x; i < 384 * 1280; i += gridDim.x * blockDim.x) {
        int o = i / 1280, k = i % 1280;
        float x = (k < 1024) ? W12[(o + 128) * 1024 + k] : Wm2[(o + 128) * 256 + (k - 1024)];
        __nv_bfloat16 h = __float2bfloat16(x);
        __nv_bfloat16 l = __float2bfloat16(x - __bfloat162float(h));
        __nv_bfloat16* d = g_Wt3 + (size_t)o * 3840 + k;
        d[0] = h; d[1280] = l; d[2560] = h;
    }
}

// tail A: [v1|mem] -> [Ah|Ah|Al] over K=1280
__global__ void tailA_kernel() {
    for (int i = blockIdx.x * blockDim.x + threadIdx.x; i < NROWS * 1280; i += gridDim.x * blockDim.x) {
        int r = i / 1280, k = i % 1280;
        float x = (k < 1024) ? g_v1all[(size_t)r * 1024 + k] : g_memall[(size_t)r * 256 + (k - 1024)];
        __nv_bfloat16 h = __float2bfloat16(x);
        __nv_bfloat16 l = __float2bfloat16(x - __bfloat162float(h));
        __nv_bfloat16* d = g_At3 + (size_t)r * 3840 + k;
        d[0] = h; d[1280] = h; d[2560] = l;
    }
}

// ---------------- bf16 tensor-core GEMM: C[m][n] = sum_k A[m][k]*W[n][k] (+bias/+addm) ----
__global__ void __launch_bounds__(256) hgemm_kernel(const __nv_bfloat16* __restrict__ A,
                                                    const __nv_bfloat16* __restrict__ W, int K,
                                                    float* __restrict__ C, int ldc,
                                                    const float* __restrict__ bias,
                                                    const float* __restrict__ addm, int addld) {
    __shared__ __nv_bfloat16 sA[2][128][40];
    __shared__ __nv_bfloat16 sW[2][128][40];
    const int tid = threadIdx.x;
    const int m0 = blockIdx.x * 128, n0 = blockIdx.y * 128;
    const int warp = tid >> 5, lane = tid & 31;
    const int wm = (warp >> 1) * 32, wn = (warp & 1) * 64;
    const int lr = tid >> 1, lc = (tid & 1) * 16;   // 2 threads/row, 16 bf16 each
    float acc[2][8][4] = {};
    const __nv_bfloat16* Ag = A + (size_t)(m0 + lr) * K + lc;
    const __nv_bfloat16* Wg = W + (size_t)(n0 + lr) * K + lc;
    uint4 ra0 = *(const uint4*)Ag, ra1 = *(const uint4*)(Ag + 8);
    uint4 rw0 = *(const uint4*)Wg, rw1 = *(const uint4*)(Wg + 8);
    *(uint4*)&sA[0][lr][lc] = ra0; *(uint4*)&sA[0][lr][lc + 8] = ra1;
    *(uint4*)&sW[0][lr][lc] = rw0; *(uint4*)&sW[0][lr][lc + 8] = rw1;
    __syncthreads();
    const int nsteps = K / 32;
    for (int s = 0; s < nsteps; s++) {
        const int cur = s & 1;
        if (s + 1 < nsteps) {
            const __nv_bfloat16* An = Ag + (size_t)(s + 1) * 32;
            const __nv_bfloat16* Wn = Wg + (size_t)(s + 1) * 32;
            ra0 = *(const uint4*)An; ra1 = *(const uint4*)(An + 8);
            rw0 = *(const uint4*)Wn; rw1 = *(const uint4*)(Wn + 8);
        }
#pragma unroll
        for (int kf = 0; kf < 2; kf++) {
            const int acol = kf * 16 + (lane & 3) * 2;
            const int arow = wm + (lane >> 2);
            uint32_t af[2][4], bfr[8][2];
#pragma unroll
            for (int mi = 0; mi < 2; mi++) {
                af[mi][0] = *(uint32_t*)&sA[cur][arow + mi * 16][acol];
                af[mi][1] = *(uint32_t*)&sA[cur][arow + mi * 16 + 8][acol];
                af[mi][2] = *(uint32_t*)&sA[cur][arow + mi * 16][acol + 8];
                af[mi][3] = *(uint32_t*)&sA[cur][arow + mi * 16 + 8][acol + 8];
            }
#pragma unroll
            for (int ni = 0; ni < 8; ni++) {
                bfr[ni][0] = *(uint32_t*)&sW[cur][wn + ni * 8 + (lane >> 2)][acol];
                bfr[ni][1] = *(uint32_t*)&sW[cur][wn + ni * 8 + (lane >> 2)][acol + 8];
            }
#pragma unroll
            for (int mi = 0; mi < 2; mi++)
#pragma unroll
                for (int ni = 0; ni < 8; ni++)
                    asm volatile(
                        "mma.sync.aligned.m16n8k16.row.col.f32.bf16.bf16.f32 "
                        "{%0,%1,%2,%3}, {%4,%5,%6,%7}, {%8,%9}, {%0,%1,%2,%3};"
                        : "+f"(acc[mi][ni][0]), "+f"(acc[mi][ni][1]),
                          "+f"(acc[mi][ni][2]), "+f"(acc[mi][ni][3])
                        : "r"(af[mi][0]), "r"(af[mi][1]), "r"(af[mi][2]), "r"(af[mi][3]),
                          "r"(bfr[ni][0]), "r"(bfr[ni][1]));
        }
        __syncthreads();
        if (s + 1 < nsteps) {
            *(uint4*)&sA[cur ^ 1][lr][lc] = ra0; *(uint4*)&sA[cur ^ 1][lr][lc + 8] = ra1;
            *(uint4*)&sW[cur ^ 1][lr][lc] = rw0; *(uint4*)&sW[cur ^ 1][lr][lc + 8] = rw1;
        }
        __syncthreads();
    }
    const int r0 = lane >> 2, c0 = (lane & 3) * 2;
#pragma unroll
    for (int mi = 0; mi < 2; mi++)
#pragma unroll
        for (int ni = 0; ni < 8; ni++) {
            int gr = m0 + wm + mi * 16 + r0;
            int gc = wn + ni * 8 + c0;
            float v0 = acc[mi][ni][0], v1 = acc[mi][ni][1];
            float v2 = acc[mi][ni][2], v3 = acc[mi][ni][3];
            int gcg = n0 + gc;
            if (bias) {
                float2 bb = *(const float2*)&bias[gcg];
                v0 += bb.x; v1 += bb.y; v2 += bb.x; v3 += bb.y;
            }
            if (addm) {
                float2 a0 = *(const float2*)&addm[(size_t)gr * addld + gcg];
                float2 a1 = *(const float2*)&addm[(size_t)(gr + 8) * addld + gcg];
                v0 += a0.x; v1 += a0.y; v2 += a1.x; v3 += a1.y;
            }
            *(float2*)&C[(size_t)gr * ldc + gcg] = make_float2(v0, v1);
            *(float2*)&C[(size_t)(gr + 8) * ldc + gcg] = make_float2(v2, v3);
        }
}

// ---------------- persistent recurrent loop (unchanged, passing) ----------------
__device__ __forceinline__ void gbar(unsigned target) {
    __syncthreads();
    if (threadIdx.x == 0) {
        __threadfence();
        atomicAdd(&g_barCnt, 1u);
        while (*(volatile unsigned*)&g_barCnt < target) { }
    }
    __syncthreads();
}

__global__ void __launch_bounds__(256, 1) loop_kernel(const float* __restrict__ Wm1,
                                                      const float* __restrict__ W12,
                                                      const float* __restrict__ Wm2,
                                                      float* __restrict__ out) {
    __shared__ float sIn[64 * 64];
    __shared__ float sWA[32 * 64];
    __shared__ float sWB[64 * 16];
    __shared__ float sWC[32 * 8];

    const int tid = threadIdx.x, blk = blockIdx.x;
    const int ht = blk >> 3, mcc = blk & 7;
    const int otile = blk >> 4, kc = blk & 15;
    const int hy = tid >> 4, bx = tid & 15;
    const int oy = tid >> 5, b2 = tid & 31;

    for (int i = tid; i < 32 * 64; i += 256) {
        int m = i >> 6, h = i & 63;
        sWA[i] = Wm1[(ht * 64 + h) * 256 + mcc * 32 + m];
    }
    for (int i = tid; i < 64 * 16; i += 256) {
        int k = i >> 4, o = i & 15;
        sWB[i] = W12[(otile * 16 + o) * 1024 + kc * 64 + k];
    }
    for (int i = tid; i < 32 * 8; i += 256) {
        int m = i >> 3, o = i & 7;
        sWC[i] = Wm2[(ht * 8 + o) * 256 + mcc * 32 + m];
    }
    __syncthreads();

    unsigned tgt = 128;
    for (int t = 0; t < NT; t++) {
        const int par = t & 1, nxt = par ^ 1;
        for (int i = tid; i < 512; i += 256) {
            int m = i >> 4, b4 = (i & 15) * 4;
            *(float4*)&sIn[m * 64 + b4] = __ldcg((const float4*)&g_memT[par][(mcc * 32 + m) * 64 + b4]);
        }
        __syncthreads();
        if (ht == 0) {
            for (int i = tid; i < 2048; i += 256) {
                int b = i >> 5, m = i & 31;
                __stcg(&g_memall[(b * NT + t) * 256 + mcc * 32 + m], sIn[m * 64 + b]);
            }
        }
        {
            float acc[4][4] = {};
#pragma unroll 8
            for (int m = 0; m < 32; m++) {
                float4 w = *(float4*)&sWA[m * 64 + hy * 4];
                float4 x = *(float4*)&sIn[m * 64 + bx * 4];
                acc[0][0] += w.x * x.x; acc[0][1] += w.x * x.y; acc[0][2] += w.x * x.z; acc[0][3] += w.x * x.w;
                acc[1][0] += w.y * x.x; acc[1][1] += w.y * x.y; acc[1][2] += w.y * x.z; acc[1][3] += w.y * x.w;
                acc[2][0] += w.z * x.x; acc[2][1] += w.z * x.y; acc[2][2] += w.z * x.z; acc[2][3] += w.z * x.w;
                acc[3][0] += w.w * x.x; acc[3][1] += w.w * x.y; acc[3][2] += w.w * x.z; acc[3][3] += w.w * x.w;
            }
#pragma unroll
            for (int i = 0; i < 4; i++)
                __stcg((float4*)&g_Apart[(mcc * 1024 + ht * 64 + hy * 4 + i) * 64 + bx * 4],
                       make_float4(acc[i][0], acc[i][1], acc[i][2], acc[i][3]));
        }
        {
            int b = tid & 63, og = (tid >> 6) * 2;
            float a0 = 0.f, a1 = 0.f;
#pragma unroll 8
            for (int m = 0; m < 32; m++) {
                float x = sIn[m * 64 + b];
                a0 += sWC[m * 8 + og] * x;
                a1 += sWC[m * 8 + og + 1] * x;
            }
            __stcg(&g_Bpart[((16 + mcc) * 128 + ht * 8 + og) * 64 + b], a0);
            __stcg(&g_Bpart[((16 + mcc) * 128 + ht * 8 + og + 1) * 64 + b], a1);
        }
        gbar(tgt); tgt += 128;
        {
            int b = tid >> 2, h0 = blk * 8 + (tid & 3) * 2;
            int row = b * NT + t;
            float2 p = __ldcg((const float2*)&g_pre1[row * 1024 + h0]);
            float s0 = p.x, s1 = p.y;
#pragma unroll
            for (int mc = 0; mc < 8; mc++) {
                s0 += __ldcg(&g_Apart[(mc * 1024 + h0) * 64 + b]);
                s1 += __ldcg(&g_Apart[(mc * 1024 + h0 + 1) * 64 + b]);
            }
            if (h0 < 512) { s0 = tanhf(s0); s1 = tanhf(s1); }
            else { s0 = fmaxf(s0, 0.f); s1 = fmaxf(s1, 0.f); }
            __stcg(&g_v1T[h0 * 64 + b], s0);
            __stcg(&g_v1T[(h0 + 1) * 64 + b], s1);
            __stcg((float2*)&g_v1all[row * 1024 + h0], make_float2(s0, s1));
            if (h0 < 128) {
                __stcg(&g_memT[nxt][h0 * 64 + b], s0);
                __stcg(&g_memT[nxt][(h0 + 1) * 64 + b], s1);
            }
        }
        gbar(tgt); tgt += 128;
        for (int i = tid; i < 1024; i += 256) {
            int k = i >> 4, b4 = (i & 15) * 4;
            *(float4*)&sIn[k * 64 + b4] = __ldcg((const float4*)&g_v1T[(kc * 64 + k) * 64 + b4]);
        }
        __syncthreads();
        {
            float a00 = 0.f, a01 = 0.f, a10 = 0.f, a11 = 0.f;
#pragma unroll 8
            for (int k = 0; k < 64; k++) {
                float2 w = *(float2*)&sWB[k * 16 + oy * 2];
                float2 x = *(float2*)&sIn[k * 64 + b2 * 2];
                a00 += w.x * x.x; a01 += w.x * x.y;
                a10 += w.y * x.x; a11 += w.y * x.y;
            }
            int ob = (kc * 128 + otile * 16 + oy * 2) * 64 + b2 * 2;
            __stcg(&g_Bpart[ob], a00);       __stcg(&g_Bpart[ob + 1], a01);
            __stcg(&g_Bpart[ob + 64], a10);  __stcg(&g_Bpart[ob + 65], a11);
        }
        gbar(tgt); tgt += 128;
        if (tid < 64) {
            int o = blk, b = tid;
            int row = b * NT + t;
            float s = __ldcg(&g_pre2[row * 512 + o]);
#pragma unroll
            for (int p = 0; p < 24; p++) s += __ldcg(&g_Bpart[(p * 128 + o) * 64 + b]);
            s = 1.f / (1.f + expf(-s));
            __stcg(&out[row * 512 + o], s);
            __stcg(&g_memT[nxt][(128 + o) * 64 + b], s);
        }
        gbar(tgt); tgt += 128;
    }
}

// ---------------- launch ----------------
extern "C" void kernel_launch(void* const* d_in, const int* in_sizes, int n_in,
                              void* d_out, int out_size) {
    const float* X   = (const float*)d_in[0];
    const float* mem = (const float*)d_in[1];
    const float* W01 = (const float*)d_in[2];
    const float* b01 = (const float*)d_in[3];
    const float* W02 = (const float*)d_in[4];
    const float* b02 = (const float*)d_in[5];
    const float* W12 = (const float*)d_in[6];
    const float* b12 = (const float*)d_in[7];
    const float* Wm1 = (const float*)d_in[8];
    const float* bm1 = (const float*)d_in[9];
    const float* Wm2 = (const float*)d_in[10];
    const float* bm2 = (const float*)d_in[11];
    float* out = (float*)d_out;

    float *pre1, *pre2, *b1, *b2;
    __nv_bfloat16 *X3, *W013, *W023, *Wt3, *At3;
    cudaGetSymbolAddress((void**)&pre1, g_pre1);
    cudaGetSymbolAddress((void**)&pre2, g_pre2);
    cudaGetSymbolAddress((void**)&b1, g_bias1);
    cudaGetSymbolAddress((void**)&b2, g_bias2);
    cudaGetSymbolAddress((void**)&X3, g_X3);
    cudaGetSymbolAddress((void**)&W013, g_W013);
    cudaGetSymbolAddress((void**)&W023, g_W023);
    cudaGetSymbolAddress((void**)&Wt3, g_Wt3);
    cudaGetSymbolAddress((void**)&At3, g_At3);

    prep_kernel<<<32, 256>>>(b01, bm1, b02, b12, bm2, mem);
    split3_kernel<<<2048, 256>>>(X, X3, 512, NROWS * 512, 1);
    split3_kernel<<<512, 256>>>(W01, W013, 512, 1024 * 512, 0);
    split3_kernel<<<256, 256>>>(W02, W023, 512, 512 * 512, 0);
    splitWtail_kernel<<<512, 256>>>(W12, Wm2);
    hgemm_kernel<<<dim3(NROWS / 128, 8), 256>>>(X3, W013, 1536, pre1, 1024, b1, nullptr, 0);
    hgemm_kernel<<<dim3(NROWS / 128, 4), 256>>>(X3, W023, 1536, pre2, 512, b2, nullptr, 0);
    loop_kernel<<<128, 256>>>(Wm1, W12, Wm2, out);
    tailA_kernel<<<2048, 256>>>();
    hgemm_kernel<<<dim3(NROWS / 128, 3), 256>>>(At3, Wt3, 3840, out + 128, 512,
                                                nullptr, pre2 + 128, 512);
}